// round 5
// baseline (speedup 1.0000x reference)
#include <cuda_runtime.h>
#include <math.h>

// BezierRenderer: 16 batches, 512x512, 10 segments.
//  1) setup_kernel <<<16, 256>>>: per-batch segment params + per-tile segment masks
//  2) render_kernel <<<(8,8,16), 256>>>: each block = 64x64 px = 4 sub-tiles of
//     64x16. Unconditional zero store first (latency-free), then mask-driven
//     recompute of active sub-tiles only.
// Mask layout: g_mask[b*256 + tx*32 + ty]  (ty fastest -> uint4 load of 4 sub-tiles)

#define NSEG    10
#define NBATCH  16
#define NTILES  (256 * NBATCH)
#define SIZEI   512

struct SegParams {
    float4 seg[NSEG];        // {vy, vx, dy, dx}
    float  id2[NSEG];
    float  thick, invthick;
};

__device__ SegParams g_params[NBATCH];
__device__ unsigned int g_mask[NTILES];

// ---------------------------------------------------------------------------
__global__ void __launch_bounds__(256)
setup_kernel(const float* __restrict__ traj,
             const float* __restrict__ thk)
{
    __shared__ float s_py[NSEG + 1], s_px[NSEG + 1];
    __shared__ float s_vy[NSEG], s_vx[NSEG], s_dy[NSEG], s_dx[NSEG], s_id2[NSEG];
    __shared__ float s_thick;

    const int b   = blockIdx.x;
    const int tid = threadIdx.x;

    if (tid <= NSEG) {
        float sy, sx;
        if (tid < NSEG) {
            const int start[4] = {10, 6, 3, 0};
            sy = 0.f; sx = 0.f;
#pragma unroll
            for (int i = 0; i < 4; i++) {
                float n = (float)(start[i] + tid) - 9.5f;
                float w = 0.75f * expf(-0.125f * n * n);   // exp(-0.5*(n/2)^2)
                sy += traj[b * 8 + i]     * w;
                sx += traj[b * 8 + 4 + i] * w;
            }
        } else {
            sy = traj[b * 8 + 3];
            sx = traj[b * 8 + 7];
        }
        s_py[tid] = sy * 512.f;
        s_px[tid] = sx * 512.f;
    }
    if (tid == 0) {
        float th = 0.f;
#pragma unroll
        for (int k = 0; k < 4; k++) th += thk[b * 4 + k] * 2.f + 0.5f;
        float t2 = 2.f * th;
        s_thick = t2;
        g_params[b].thick    = t2;
        g_params[b].invthick = 1.f / t2;
    }
    __syncthreads();

    if (tid < NSEG) {
        float vy = s_py[tid], vx = s_px[tid];
        float dy = s_py[tid + 1] - vy;
        float dx = s_px[tid + 1] - vx;
        float id2 = 1.f / (dy * dy + dx * dx + 1e-5f);
        s_vy[tid] = vy;  s_vx[tid] = vx;
        s_dy[tid] = dy;  s_dx[tid] = dx;
        s_id2[tid] = id2;
        g_params[b].seg[tid] = make_float4(vy, vx, dy, dx);
        g_params[b].id2[tid] = id2;
    }
    __syncthreads();

    // One tile per thread: tx = tid>>5 (0..7), ty = tid&31 (0..31).
    // Tile 64x16, center (tx*64+31.5, ty*16+7.5); max px-to-center dist
    // sqrt(31.5^2+7.5^2)=32.38 < 33. Segment in mask iff dist(center,seg) < thick+33.
    const int tx = tid >> 5, ty = tid & 31;
    const float cx = (float)(tx << 6) + 31.5f;
    const float cy = (float)(ty << 4) + 7.5f;
    const float lim = s_thick + 33.0f;
    const float lim2 = lim * lim;

    unsigned int m = 0;
#pragma unroll
    for (int j = 0; j < NSEG; j++) {
        float ay = cy - s_vy[j];
        float ax = cx - s_vx[j];
        float dot = ay * s_dy[j] + ax * s_dx[j];
        float t = fminf(fmaxf(dot * s_id2[j], 0.f), 1.f);
        float ry = fmaf(-t, s_dy[j], ay);
        float rx = fmaf(-t, s_dx[j], ax);
        if (fmaf(ry, ry, rx * rx) < lim2) m |= (1u << j);
    }
    g_mask[b * 256 + tid] = m;    // tid == tx*32 + ty
}

// ---------------------------------------------------------------------------
// Render one 64x16 sub-tile for this thread's 4 pixels (device inline).
// ---------------------------------------------------------------------------
__device__ __forceinline__ void render_subtile(
    unsigned int mask, const SegParams* __restrict__ sp,
    float thick, float invthick,
    float yf, float x0, float* outp)
{
    float m0 = 1e30f, m1 = 1e30f, m2 = 1e30f, m3 = 1e30f;

    while (mask) {
        const int j = __ffs(mask) - 1;
        mask &= mask - 1;

        const float4 s  = __ldg(&sp->seg[j]);   // {vy, vx, dy, dx}
        const float ij  = __ldg(&sp->id2[j]);
        const float vjx = s.y, djy = s.z, djx = s.w;

        const float ay  = yf - s.x;
        const float cyd = ay * djy;

        {
            float pvx = x0 - vjx;
            float dot = fmaf(pvx, djx, cyd);
            float t   = fminf(fmaxf(dot * ij, 0.f), 1.f);
            float ry  = fmaf(-t, djy, ay);
            float rx  = fmaf(-t, djx, pvx);
            m0 = fminf(m0, fmaf(ry, ry, rx * rx));
        }
        {
            float pvx = x0 + 1.f - vjx;
            float dot = fmaf(pvx, djx, cyd);
            float t   = fminf(fmaxf(dot * ij, 0.f), 1.f);
            float ry  = fmaf(-t, djy, ay);
            float rx  = fmaf(-t, djx, pvx);
            m1 = fminf(m1, fmaf(ry, ry, rx * rx));
        }
        {
            float pvx = x0 + 2.f - vjx;
            float dot = fmaf(pvx, djx, cyd);
            float t   = fminf(fmaxf(dot * ij, 0.f), 1.f);
            float ry  = fmaf(-t, djy, ay);
            float rx  = fmaf(-t, djx, pvx);
            m2 = fminf(m2, fmaf(ry, ry, rx * rx));
        }
        {
            float pvx = x0 + 3.f - vjx;
            float dot = fmaf(pvx, djx, cyd);
            float t   = fminf(fmaxf(dot * ij, 0.f), 1.f);
            float ry  = fmaf(-t, djy, ay);
            float rx  = fmaf(-t, djx, pvx);
            m3 = fminf(m3, fmaf(ry, ry, rx * rx));
        }
    }

    float4 res;
    res.x = fminf(fmaxf((thick - sqrtf(m0)) * invthick, 0.f), 1.f);
    res.y = fminf(fmaxf((thick - sqrtf(m1)) * invthick, 0.f), 1.f);
    res.z = fminf(fmaxf((thick - sqrtf(m2)) * invthick, 0.f), 1.f);
    res.w = fminf(fmaxf((thick - sqrtf(m3)) * invthick, 0.f), 1.f);
    *reinterpret_cast<float4*>(outp) = res;
}

// ---------------------------------------------------------------------------
// Render: block = 64x64 px (4 sub-tiles of 64x16). Zero stores issue before
// any dependency on the mask load; active sub-tiles are recomputed after.
// ---------------------------------------------------------------------------
__global__ void __launch_bounds__(256)
render_kernel(float* __restrict__ out)
{
    const int b   = blockIdx.z;
    const int tid = threadIdx.x;
    const int tx  = blockIdx.x;            // 0..7  (64 px wide)
    const int tyb = blockIdx.y;            // 0..7  (64 px tall = 4 sub-tiles)

    const int x  = (tx << 6) + (tid & 15) * 4;
    const int y0 = (tyb << 6) + (tid >> 4);          // row in sub-tile 0
    float* outp0 = out + ((size_t)b << 18) + ((size_t)y0 << 9) + x;

    // 4 sub-tile masks in one 16B load (issues immediately).
    const uint4 mv = __ldg(reinterpret_cast<const uint4*>(
        &g_mask[b * 256 + tx * 32 + tyb * 4]));

    // Unconditional zero fill: no dependency on the mask value.
    const float4 z = make_float4(0.f, 0.f, 0.f, 0.f);
    *reinterpret_cast<float4*>(outp0)            = z;
    *reinterpret_cast<float4*>(outp0 + 16 * 512) = z;
    *reinterpret_cast<float4*>(outp0 + 32 * 512) = z;
    *reinterpret_cast<float4*>(outp0 + 48 * 512) = z;

    const unsigned int any = mv.x | mv.y | mv.z | mv.w;
    if (any == 0) return;

    const SegParams* sp = &g_params[b];
    const float thick    = __ldg(&sp->thick);
    const float invthick = __ldg(&sp->invthick);
    const float x0 = (float)x;

    if (mv.x) render_subtile(mv.x, sp, thick, invthick, (float)(y0),      x0, outp0);
    if (mv.y) render_subtile(mv.y, sp, thick, invthick, (float)(y0 + 16), x0, outp0 + 16 * 512);
    if (mv.z) render_subtile(mv.z, sp, thick, invthick, (float)(y0 + 32), x0, outp0 + 32 * 512);
    if (mv.w) render_subtile(mv.w, sp, thick, invthick, (float)(y0 + 48), x0, outp0 + 48 * 512);
}

extern "C" void kernel_launch(void* const* d_in, const int* in_sizes, int n_in,
                              void* d_out, int out_size)
{
    const float* traj = (const float*)d_in[0];   // (16, 2, 4)
    const float* thk  = (const float*)d_in[1];   // (16, 1, 4)
    float* out = (float*)d_out;                  // (16, 512, 512)

    setup_kernel<<<NBATCH, 256>>>(traj, thk);

    dim3 grid(8, 8, NBATCH);                     // 1024 blocks
    render_kernel<<<grid, 256>>>(out);
}